// round 1
// baseline (speedup 1.0000x reference)
#include <cuda_runtime.h>

#define N_COLS 65536
#define BATCH   256

// Scratch for precomputed per-column coefficients {c0,c1,c2,c3} (1 MiB).
__device__ float4 g_wc[N_COLS];

// W16_TO_4 exactly as the reference builds it (note W[3,1] double-write -> 1).
__constant__ float c_W[4][16] = {
    { 0, 0, 0, 0, 0, 0, 0, 0,  1,  1,  1,  1,  1,  1,  1, 0 + 1 - 1 + 1}, // placeholder fixed below
};

// NOTE: constant array above replaced by correct literal here:
__constant__ float c_Wfull[4][16] = {
    { 0, 0, 0, 0,  0, 0, 0, 0,   1,  1,  1,  1,   1,  1,  1,  1},
    { 0, 0, 1, 1,  0, 0, 1, 1,  -1, -1,  0,  0,  -1, -1,  0,  0},
    { 0, 0, 0, 0,  1, 1, 1, 1,  -1, -1, -1, -1,   0,  0,  0,  0},
    { 0, 1,-1, 0, -1, 0,-2,-1,   1,  2,  0,  1,   0,  1, -1,  0}
};

// Kernel 1: per column n, softmax over the 16 gate logits, project to 4 coeffs.
__global__ void wc_precompute_kernel(const float* __restrict__ w) {
    int n = blockIdx.x * blockDim.x + threadIdx.x;
    if (n >= N_COLS) return;

    float v[16];
    float m = -1e30f;
#pragma unroll
    for (int k = 0; k < 16; k++) {
        v[k] = w[k * N_COLS + n];
        m = fmaxf(m, v[k]);
    }
    float s = 0.0f;
#pragma unroll
    for (int k = 0; k < 16; k++) {
        v[k] = __expf(v[k] - m);
        s += v[k];
    }
    float inv = 1.0f / s;

    float c0 = 0.f, c1 = 0.f, c2 = 0.f, c3 = 0.f;
#pragma unroll
    for (int k = 0; k < 16; k++) {
        c0 = fmaf(c_Wfull[0][k], v[k], c0);
        c1 = fmaf(c_Wfull[1][k], v[k], c1);
        c2 = fmaf(c_Wfull[2][k], v[k], c2);
        c3 = fmaf(c_Wfull[3][k], v[k], c3);
    }
    g_wc[n] = make_float4(c0 * inv, c1 * inv, c2 * inv, c3 * inv);
}

// Kernel 2: pure streaming bilinear gate.
// Each thread handles 4 output columns of one batch row:
//   reads 2x float4 from x (interleaved A,B pairs), 4x float4 coeffs (L2-hot),
//   writes 1x float4 to out.
__global__ void gate_apply_kernel(const float4* __restrict__ x,
                                  float4* __restrict__ out) {
    int c = blockIdx.x * blockDim.x + threadIdx.x;   // column-quad index [0, N/4)
    int b = blockIdx.y;                               // batch row

    const float4* xrow = x + (size_t)b * (N_COLS / 2);   // row stride 2N floats = N/2 float4
    float4 xa = __ldg(&xrow[2 * c]);       // {A0,B0,A1,B1}
    float4 xb = __ldg(&xrow[2 * c + 1]);   // {A2,B2,A3,B3}

    float4 w0 = g_wc[4 * c + 0];
    float4 w1 = g_wc[4 * c + 1];
    float4 w2 = g_wc[4 * c + 2];
    float4 w3 = g_wc[4 * c + 3];

    float4 r;
    // out = c0 + c1*A + c2*B + c3*A*B  =  fma(A, fma(B,c3,c1), fma(B,c2,c0))
    r.x = fmaf(xa.x, fmaf(xa.y, w0.w, w0.y), fmaf(xa.y, w0.z, w0.x));
    r.y = fmaf(xa.z, fmaf(xa.w, w1.w, w1.y), fmaf(xa.w, w1.z, w1.x));
    r.z = fmaf(xb.x, fmaf(xb.y, w2.w, w2.y), fmaf(xb.y, w2.z, w2.x));
    r.w = fmaf(xb.z, fmaf(xb.w, w3.w, w3.y), fmaf(xb.w, w3.z, w3.x));

    out[(size_t)b * (N_COLS / 4) + c] = r;
}

extern "C" void kernel_launch(void* const* d_in, const int* in_sizes, int n_in,
                              void* d_out, int out_size) {
    const float* x = (const float*)d_in[0];   // (256, 131072)
    const float* w = (const float*)d_in[1];   // (16, 65536)
    float* out = (float*)d_out;               // (256, 65536)

    // Kernel 1: one thread per column.
    wc_precompute_kernel<<<N_COLS / 256, 256>>>(w);

    // Kernel 2: grid (N/4/256, batch) = (64, 256), 256 threads/block.
    dim3 grid(N_COLS / 4 / 256, BATCH);
    gate_apply_kernel<<<grid, 256>>>((const float4*)x, (float4*)out);
}

// round 2
// speedup vs baseline: 1.1607x; 1.1607x over previous
#include <cuda_runtime.h>

#define N_COLS 65536
#define BATCH   256
#define ROWS_PER_BLOCK 16
#define THREADS 256

// Precomputed per-column coefficients {c0,c1,c2,c3} (1 MiB), indexed by column.
__device__ float4 g_wc[N_COLS];

// W16_TO_4 exactly as the reference builds it (W[3,1] written twice -> final 1).
__constant__ float c_W[4][16] = {
    { 0, 0, 0, 0,  0, 0, 0, 0,   1,  1,  1,  1,   1,  1,  1,  1},
    { 0, 0, 1, 1,  0, 0, 1, 1,  -1, -1,  0,  0,  -1, -1,  0,  0},
    { 0, 0, 0, 0,  1, 1, 1, 1,  -1, -1, -1, -1,   0,  0,  0,  0},
    { 0, 1,-1, 0, -1, 0,-2,-1,   1,  2,  0,  1,   0,  1, -1,  0}
};

// Kernel 1: softmax over 16 gate logits per column, project to 4 coeffs.
// Vectorized: each thread handles 4 consecutive columns via float4 loads.
__global__ void wc_precompute_kernel(const float4* __restrict__ w4) {
    int q = blockIdx.x * blockDim.x + threadIdx.x;   // column-quad [0, N/4)
    if (q >= N_COLS / 4) return;

    float4 v[16];
    float4 m = make_float4(-1e30f, -1e30f, -1e30f, -1e30f);
#pragma unroll
    for (int k = 0; k < 16; k++) {
        v[k] = w4[k * (N_COLS / 4) + q];
        m.x = fmaxf(m.x, v[k].x); m.y = fmaxf(m.y, v[k].y);
        m.z = fmaxf(m.z, v[k].z); m.w = fmaxf(m.w, v[k].w);
    }
    float4 s = make_float4(0.f, 0.f, 0.f, 0.f);
#pragma unroll
    for (int k = 0; k < 16; k++) {
        v[k].x = __expf(v[k].x - m.x); s.x += v[k].x;
        v[k].y = __expf(v[k].y - m.y); s.y += v[k].y;
        v[k].z = __expf(v[k].z - m.z); s.z += v[k].z;
        v[k].w = __expf(v[k].w - m.w); s.w += v[k].w;
    }
    float4 inv = make_float4(1.f / s.x, 1.f / s.y, 1.f / s.z, 1.f / s.w);

    float c[4][4] = {};   // [coef][lane-within-quad]
#pragma unroll
    for (int k = 0; k < 16; k++) {
#pragma unroll
        for (int j = 0; j < 4; j++) {
            float wk = c_W[j][k];
            c[j][0] = fmaf(wk, v[k].x, c[j][0]);
            c[j][1] = fmaf(wk, v[k].y, c[j][1]);
            c[j][2] = fmaf(wk, v[k].z, c[j][2]);
            c[j][3] = fmaf(wk, v[k].w, c[j][3]);
        }
    }
    g_wc[4 * q + 0] = make_float4(c[0][0] * inv.x, c[1][0] * inv.x, c[2][0] * inv.x, c[3][0] * inv.x);
    g_wc[4 * q + 1] = make_float4(c[0][1] * inv.y, c[1][1] * inv.y, c[2][1] * inv.y, c[3][1] * inv.y);
    g_wc[4 * q + 2] = make_float4(c[0][2] * inv.z, c[1][2] * inv.z, c[2][2] * inv.z, c[3][2] * inv.z);
    g_wc[4 * q + 3] = make_float4(c[0][3] * inv.w, c[1][3] * inv.w, c[2][3] * inv.w, c[3][3] * inv.w);
}

// Kernel 2: streaming bilinear gate, restructured for L1 efficiency.
//
// x as float4: quad q = {A(2q), B(2q), A(2q+1), B(2q+1)} -> columns 2q, 2q+1.
// Each thread owns TWO x-quads: q0 = base + t, q1 = base + THREADS + t, so
// every LDG.128 is unit-stride across the warp (512B contiguous per warp).
// Coefficients for the thread's 4 columns are loaded ONCE into registers and
// reused across ROWS_PER_BLOCK batch rows. Outputs are float2 stores
// (columns 2q..2q+1 contiguous), fully coalesced.
__global__ void __launch_bounds__(THREADS)
gate_apply_kernel(const float4* __restrict__ x, float2* __restrict__ out) {
    const int t  = threadIdx.x;
    const int q0 = blockIdx.x * (2 * THREADS) + t;       // x-quad index
    const int q1 = q0 + THREADS;
    const int b0 = blockIdx.y * ROWS_PER_BLOCK;

    // Coefficients for 4 columns: 2*q0, 2*q0+1, 2*q1, 2*q1+1
    const float4 wA0 = g_wc[2 * q0];
    const float4 wA1 = g_wc[2 * q0 + 1];
    const float4 wB0 = g_wc[2 * q1];
    const float4 wB1 = g_wc[2 * q1 + 1];

    const float4* xq0 = x + (size_t)b0 * (N_COLS / 2) + q0;
    const float4* xq1 = x + (size_t)b0 * (N_COLS / 2) + q1;
    float2* oq0 = out + (size_t)b0 * (N_COLS / 2) + q0;
    float2* oq1 = out + (size_t)b0 * (N_COLS / 2) + q1;

#pragma unroll 4
    for (int r = 0; r < ROWS_PER_BLOCK; r++) {
        float4 xa = __ldg(xq0);   // {A,B,A',B'} for columns 2q0, 2q0+1
        float4 xb = __ldg(xq1);   // columns 2q1, 2q1+1

        float2 ra, rb;
        // out = c0 + c1*A + c2*B + c3*A*B = fma(A, fma(B,c3,c1), fma(B,c2,c0))
        ra.x = fmaf(xa.x, fmaf(xa.y, wA0.w, wA0.y), fmaf(xa.y, wA0.z, wA0.x));
        ra.y = fmaf(xa.z, fmaf(xa.w, wA1.w, wA1.y), fmaf(xa.w, wA1.z, wA1.x));
        rb.x = fmaf(xb.x, fmaf(xb.y, wB0.w, wB0.y), fmaf(xb.y, wB0.z, wB0.x));
        rb.y = fmaf(xb.z, fmaf(xb.w, wB1.w, wB1.y), fmaf(xb.w, wB1.z, wB1.x));

        *oq0 = ra;
        *oq1 = rb;

        xq0 += N_COLS / 2;  xq1 += N_COLS / 2;
        oq0 += N_COLS / 2;  oq1 += N_COLS / 2;
    }
}

extern "C" void kernel_launch(void* const* d_in, const int* in_sizes, int n_in,
                              void* d_out, int out_size) {
    const float* x = (const float*)d_in[0];   // (256, 131072)
    const float* w = (const float*)d_in[1];   // (16, 65536)
    float* out = (float*)d_out;               // (256, 65536)

    wc_precompute_kernel<<<(N_COLS / 4) / 256, 256>>>((const float4*)w);

    // grid.x: 32768 x-quads per row / (2*256 per block) = 64; grid.y: 256/16 = 16
    dim3 grid((N_COLS / 2) / (2 * THREADS), BATCH / ROWS_PER_BLOCK);
    gate_apply_kernel<<<grid, THREADS>>>((const float4*)x, (float2*)out);
}

// round 3
// speedup vs baseline: 1.2707x; 1.0948x over previous
#include <cuda_runtime.h>

#define N_COLS 65536
#define BATCH   256
#define ROWS_PER_BLOCK 8
#define THREADS 256

// Precomputed per-column coefficients {c0,c1,c2,c3} (1 MiB), indexed by column.
__device__ float4 g_wc[N_COLS];

// W16_TO_4 exactly as the reference builds it (W[3,1] written twice -> final 1).
__constant__ float c_W[4][16] = {
    { 0, 0, 0, 0,  0, 0, 0, 0,   1,  1,  1,  1,   1,  1,  1,  1},
    { 0, 0, 1, 1,  0, 0, 1, 1,  -1, -1,  0,  0,  -1, -1,  0,  0},
    { 0, 0, 0, 0,  1, 1, 1, 1,  -1, -1, -1, -1,   0,  0,  0,  0},
    { 0, 1,-1, 0, -1, 0,-2,-1,   1,  2,  0,  1,   0,  1, -1,  0}
};

// Kernel 1: per-column softmax over 16 logits + 4x16 projection.
// One column per thread: 65536 threads = 256 CTAs (full chip), warp loads are
// 128B unit-stride per k. 16 independent loads per thread hide DRAM latency.
__global__ void wc_precompute_kernel(const float* __restrict__ w) {
    int n = blockIdx.x * blockDim.x + threadIdx.x;

    float v[16];
    float m = -1e30f;
#pragma unroll
    for (int k = 0; k < 16; k++) {
        v[k] = __ldg(&w[k * N_COLS + n]);
        m = fmaxf(m, v[k]);
    }
    float s = 0.0f;
#pragma unroll
    for (int k = 0; k < 16; k++) {
        v[k] = __expf(v[k] - m);
        s += v[k];
    }
    float inv = 1.0f / s;

    float c0 = 0.f, c1 = 0.f, c2 = 0.f, c3 = 0.f;
#pragma unroll
    for (int k = 0; k < 16; k++) {
        c0 = fmaf(c_W[0][k], v[k], c0);
        c1 = fmaf(c_W[1][k], v[k], c1);
        c2 = fmaf(c_W[2][k], v[k], c2);
        c3 = fmaf(c_W[3][k], v[k], c3);
    }
    g_wc[n] = make_float4(c0 * inv, c1 * inv, c2 * inv, c3 * inv);
}

// Kernel 2: streaming bilinear gate.
// x as float4: quad q = {A(2q), B(2q), A(2q+1), B(2q+1)} -> columns 2q, 2q+1.
// Each thread owns TWO x-quads (q0 = base+t, q1 = base+THREADS+t) so every
// LDG.128 is unit-stride across the warp. Coefficients for the thread's 4
// columns live in registers across ROWS_PER_BLOCK batch rows. Fully unrolled
// row loop batches the 16 LDGs for deep MLP.
__global__ void __launch_bounds__(THREADS)
gate_apply_kernel(const float4* __restrict__ x, float2* __restrict__ out) {
    const int t  = threadIdx.x;
    const int q0 = blockIdx.x * (2 * THREADS) + t;       // x-quad index
    const int q1 = q0 + THREADS;
    const int b0 = blockIdx.y * ROWS_PER_BLOCK;

    // Coefficients for 4 columns: 2*q0, 2*q0+1, 2*q1, 2*q1+1
    const float4 wA0 = g_wc[2 * q0];
    const float4 wA1 = g_wc[2 * q0 + 1];
    const float4 wB0 = g_wc[2 * q1];
    const float4 wB1 = g_wc[2 * q1 + 1];

    const float4* xq0 = x + (size_t)b0 * (N_COLS / 2) + q0;
    const float4* xq1 = x + (size_t)b0 * (N_COLS / 2) + q1;
    float2* oq0 = out + (size_t)b0 * (N_COLS / 2) + q0;
    float2* oq1 = out + (size_t)b0 * (N_COLS / 2) + q1;

#pragma unroll
    for (int r = 0; r < ROWS_PER_BLOCK; r++) {
        float4 xa = __ldg(xq0);   // {A,B,A',B'} for columns 2q0, 2q0+1
        float4 xb = __ldg(xq1);   // columns 2q1, 2q1+1

        float2 ra, rb;
        // out = c0 + c1*A + c2*B + c3*A*B = fma(A, fma(B,c3,c1), fma(B,c2,c0))
        ra.x = fmaf(xa.x, fmaf(xa.y, wA0.w, wA0.y), fmaf(xa.y, wA0.z, wA0.x));
        ra.y = fmaf(xa.z, fmaf(xa.w, wA1.w, wA1.y), fmaf(xa.w, wA1.z, wA1.x));
        rb.x = fmaf(xb.x, fmaf(xb.y, wB0.w, wB0.y), fmaf(xb.y, wB0.z, wB0.x));
        rb.y = fmaf(xb.z, fmaf(xb.w, wB1.w, wB1.y), fmaf(xb.w, wB1.z, wB1.x));

        *oq0 = ra;
        *oq1 = rb;

        xq0 += N_COLS / 2;  xq1 += N_COLS / 2;
        oq0 += N_COLS / 2;  oq1 += N_COLS / 2;
    }
}

extern "C" void kernel_launch(void* const* d_in, const int* in_sizes, int n_in,
                              void* d_out, int out_size) {
    const float* x = (const float*)d_in[0];   // (256, 131072)
    const float* w = (const float*)d_in[1];   // (16, 65536)
    float* out = (float*)d_out;               // (256, 65536)

    wc_precompute_kernel<<<N_COLS / 256, 256>>>(w);

    // grid.x: 32768 x-quads per row / (2*256 per block) = 64; grid.y: 256/8 = 32
    dim3 grid((N_COLS / 2) / (2 * THREADS), BATCH / ROWS_PER_BLOCK);
    gate_apply_kernel<<<grid, THREADS>>>((const float4*)x, (float2*)out);
}

// round 4
// speedup vs baseline: 1.3478x; 1.0607x over previous
#include <cuda_runtime.h>

#define N_COLS 65536
#define BATCH   256
#define ROWS_PER_BLOCK 8
#define THREADS 256
#define ROW_STRIDE (N_COLS / 2)   // row stride in float4 units (x) / float2 units (out)

// Precomputed per-column coefficients {c0,c1,c2,c3} (1 MiB), indexed by column.
__device__ float4 g_wc[N_COLS];

// W16_TO_4 exactly as the reference builds it (W[3,1] written twice -> final 1).
__constant__ float c_W[4][16] = {
    { 0, 0, 0, 0,  0, 0, 0, 0,   1,  1,  1,  1,   1,  1,  1,  1},
    { 0, 0, 1, 1,  0, 0, 1, 1,  -1, -1,  0,  0,  -1, -1,  0,  0},
    { 0, 0, 0, 0,  1, 1, 1, 1,  -1, -1, -1, -1,   0,  0,  0,  0},
    { 0, 1,-1, 0, -1, 0,-2,-1,   1,  2,  0,  1,   0,  1, -1,  0}
};

// Kernel 1: per-column softmax over 16 logits + 4x16 projection.
// One column per thread: 65536 threads = 256 CTAs, coalesced 128B warp loads,
// 16-deep load MLP per thread.
__global__ void wc_precompute_kernel(const float* __restrict__ w) {
    int n = blockIdx.x * blockDim.x + threadIdx.x;

    float v[16];
    float m = -1e30f;
#pragma unroll
    for (int k = 0; k < 16; k++) {
        v[k] = __ldg(&w[k * N_COLS + n]);
        m = fmaxf(m, v[k]);
    }
    float s = 0.0f;
#pragma unroll
    for (int k = 0; k < 16; k++) {
        v[k] = __expf(v[k] - m);
        s += v[k];
    }
    float inv = 1.0f / s;

    float c0 = 0.f, c1 = 0.f, c2 = 0.f, c3 = 0.f;
#pragma unroll
    for (int k = 0; k < 16; k++) {
        c0 = fmaf(c_W[0][k], v[k], c0);
        c1 = fmaf(c_W[1][k], v[k], c1);
        c2 = fmaf(c_W[2][k], v[k], c2);
        c3 = fmaf(c_W[3][k], v[k], c3);
    }
    g_wc[n] = make_float4(c0 * inv, c1 * inv, c2 * inv, c3 * inv);
}

// Kernel 2: streaming bilinear gate with deep load batching.
// Each thread owns TWO x-quads (q0 = base+t, q1 = base+THREADS+t) -> every
// LDG.128 unit-stride across the warp. Coefficients stay in registers across
// all ROWS_PER_BLOCK rows. The row loop is processed in halves of 4 rows:
// all 8 LDG.128 issued back-to-back (deep MLP), then 8 compute+STG.64.
// __launch_bounds__(256, 4): cap regs at ~64 so 4 CTAs/SM stay resident
// (matches the occupancy we already achieve) while allowing 32 data regs.
__global__ void __launch_bounds__(THREADS, 4)
gate_apply_kernel(const float4* __restrict__ x, float2* __restrict__ out) {
    const int t  = threadIdx.x;
    const int q0 = blockIdx.x * (2 * THREADS) + t;       // x-quad index
    const int q1 = q0 + THREADS;
    const int b0 = blockIdx.y * ROWS_PER_BLOCK;

    // Coefficients for 4 columns: 2*q0, 2*q0+1, 2*q1, 2*q1+1
    const float4 wA0 = g_wc[2 * q0];
    const float4 wA1 = g_wc[2 * q0 + 1];
    const float4 wB0 = g_wc[2 * q1];
    const float4 wB1 = g_wc[2 * q1 + 1];

    const float4* xq0 = x + (size_t)b0 * ROW_STRIDE + q0;
    const float4* xq1 = x + (size_t)b0 * ROW_STRIDE + q1;
    float2* oq0 = out + (size_t)b0 * ROW_STRIDE + q0;
    float2* oq1 = out + (size_t)b0 * ROW_STRIDE + q1;

#pragma unroll
    for (int h = 0; h < ROWS_PER_BLOCK / 4; h++) {
        float4 a[4], b[4];
        // Batch all 8 loads first: 8 LDG.128 in flight per thread.
#pragma unroll
        for (int i = 0; i < 4; i++) {
            a[i] = __ldg(xq0 + (size_t)i * ROW_STRIDE);
            b[i] = __ldg(xq1 + (size_t)i * ROW_STRIDE);
        }
        // Then compute + store.
#pragma unroll
        for (int i = 0; i < 4; i++) {
            float2 ra, rb;
            // out = c0 + c1*A + c2*B + c3*A*B = fma(A, fma(B,c3,c1), fma(B,c2,c0))
            ra.x = fmaf(a[i].x, fmaf(a[i].y, wA0.w, wA0.y), fmaf(a[i].y, wA0.z, wA0.x));
            ra.y = fmaf(a[i].z, fmaf(a[i].w, wA1.w, wA1.y), fmaf(a[i].w, wA1.z, wA1.x));
            rb.x = fmaf(b[i].x, fmaf(b[i].y, wB0.w, wB0.y), fmaf(b[i].y, wB0.z, wB0.x));
            rb.y = fmaf(b[i].z, fmaf(b[i].w, wB1.w, wB1.y), fmaf(b[i].w, wB1.z, wB1.x));
            oq0[(size_t)i * ROW_STRIDE] = ra;
            oq1[(size_t)i * ROW_STRIDE] = rb;
        }
        xq0 += 4 * ROW_STRIDE;  xq1 += 4 * ROW_STRIDE;
        oq0 += 4 * ROW_STRIDE;  oq1 += 4 * ROW_STRIDE;
    }
}

extern "C" void kernel_launch(void* const* d_in, const int* in_sizes, int n_in,
                              void* d_out, int out_size) {
    const float* x = (const float*)d_in[0];   // (256, 131072)
    const float* w = (const float*)d_in[1];   // (16, 65536)
    float* out = (float*)d_out;               // (256, 65536)

    wc_precompute_kernel<<<N_COLS / 256, 256>>>(w);

    // grid: (32768 quads / 512 per block, 256 rows / 8 per block) = (64, 32)
    dim3 grid((N_COLS / 2) / (2 * THREADS), BATCH / ROWS_PER_BLOCK);
    gate_apply_kernel<<<grid, THREADS>>>((const float4*)x, (float2*)out);
}